// round 15
// baseline (speedup 1.0000x reference)
#include <cuda_runtime.h>
#include <cuda_bf16.h>
#include <math.h>
#include <stdint.h>

#define NB   2
#define NT   1024
#define ND   2048
#define NH   16
#define NDK  128
#define NTOK (NB*NT)      /* 2048 tokens */
#define NC   (NH*NDK)     /* 2048 channels */
#define KS   (3*ND)       /* 6144: split-precision K (hi|lo|hi) */
#define WSTRIDE ((size_t)NC*KS)

// ------------------------------------------------------------------
// Scratch (device globals; no runtime allocation allowed)
// ------------------------------------------------------------------
__device__ __nv_bfloat16 g_xs[(size_t)NTOK*KS];            // split activations
__device__ __nv_bfloat16 g_ws[6*WSTRIDE + (size_t)128*KS]; // split weights (+Wb pad)
__device__ float g_q0[NTOK*NC];
__device__ float g_k0[NTOK*NC];
__device__ float g_v0[NTOK*NC];
__device__ float g_qc[NTOK*NC];
__device__ float g_kc[NTOK*NC];
__device__ float g_vc[NTOK*NC];
__device__ float g_a [NTOK*NC];
__device__ float g_gt[NTOK*NC];
__device__ float g_o1[NTOK*NC];                   // reduced recurrence output
__device__ float g_bt[NTOK*NH];

// ==================================================================
// Helpers
// ==================================================================
__device__ __forceinline__ uint32_t smem_u32(const void* p) {
    uint32_t r;
    asm("{ .reg .u64 t; cvta.to.shared.u64 t, %1; cvt.u32.u64 %0, t; }"
        : "=r"(r) : "l"(p));
    return r;
}
__device__ __forceinline__ void cp16(uint32_t dst, const void* src) {
    asm volatile("cp.async.cg.shared.global [%0], [%1], 16;\n" :: "r"(dst), "l"(src));
}
__device__ __forceinline__ void cp_commit() {
    asm volatile("cp.async.commit_group;\n" ::: "memory");
}
__device__ __forceinline__ void cp_wait1() {
    asm volatile("cp.async.wait_group 1;\n" ::: "memory");
}
__device__ __forceinline__ void cp_wait0() {
    asm volatile("cp.async.wait_group 0;\n" ::: "memory");
}
__device__ __forceinline__ void ldsm4(uint32_t& r0, uint32_t& r1, uint32_t& r2,
                                      uint32_t& r3, uint32_t addr) {
    asm volatile("ldmatrix.sync.aligned.m8n8.x4.shared.b16 {%0,%1,%2,%3}, [%4];"
                 : "=r"(r0), "=r"(r1), "=r"(r2), "=r"(r3) : "r"(addr));
}
__device__ __forceinline__ void mma16816(float* d, const uint32_t* a,
                                         uint32_t b0, uint32_t b1) {
    asm volatile(
        "mma.sync.aligned.m16n8k16.row.col.f32.bf16.bf16.f32 "
        "{%0,%1,%2,%3}, {%4,%5,%6,%7}, {%8,%9}, {%0,%1,%2,%3};"
        : "+f"(d[0]), "+f"(d[1]), "+f"(d[2]), "+f"(d[3])
        : "r"(a[0]), "r"(a[1]), "r"(a[2]), "r"(a[3]), "r"(b0), "r"(b1));
}
__device__ __forceinline__ float fsig(float z) {
    return 1.f / (1.f + __expf(-z));
}

// ---- packed f32x2 (sm_100-family base feature) ----
typedef unsigned long long u64;
__device__ __forceinline__ u64 pack2(float lo, float hi) {
    u64 r; asm("mov.b64 %0, {%1, %2};" : "=l"(r) : "f"(lo), "f"(hi)); return r;
}
__device__ __forceinline__ void unpack2(u64 v, float& lo, float& hi) {
    asm("mov.b64 {%0, %1}, %2;" : "=f"(lo), "=f"(hi) : "l"(v));
}
__device__ __forceinline__ u64 fma2(u64 a, u64 b, u64 c) {
    u64 d; asm("fma.rn.f32x2 %0, %1, %2, %3;" : "=l"(d) : "l"(a), "l"(b), "l"(c));
    return d;
}
__device__ __forceinline__ u64 mul2(u64 a, u64 b) {
    u64 d; asm("mul.rn.f32x2 %0, %1, %2;" : "=l"(d) : "l"(a), "l"(b));
    return d;
}
__device__ __forceinline__ u64 add2(u64 a, u64 b) {
    u64 d; asm("add.rn.f32x2 %0, %1, %2;" : "=l"(d) : "l"(a), "l"(b));
    return d;
}

// ==================================================================
// Tensor-core GEMM (HMMA): fused 6-output projection (grid.x=81) or Wo (16)
// 128x128 tile, BK=64, 3-stage cp.async pipeline (96 KB smem), 8 warps.
// (Frozen R13 configuration.)
// ==================================================================
#define BK      64
#define KITERS  (KS/BK)      /* 96 */
#define STG_B   32768
#define STAGES  3
#define TG_SMEM (STAGES*STG_B)

__global__ void __launch_bounds__(256, 2)
tgemm(const __nv_bfloat16* __restrict__ A, const __nv_bfloat16* __restrict__ Bw,
      const float* __restrict__ bias_a, const float* __restrict__ bias_b,
      float* __restrict__ Cq, float* __restrict__ Ck, float* __restrict__ Cv,
      float* __restrict__ Ca, float* __restrict__ Cg, float* __restrict__ Cb)
{
    extern __shared__ __align__(1024) char smem[];
    const uint32_t sb = smem_u32(smem);

    const int tid  = threadIdx.x;
    const int lane = tid & 31;
    const int wid  = tid >> 5;
    const int wm   = wid & 3;
    const int wn   = wid >> 2;
    const int m0   = blockIdx.y * 128;
    const int n0g  = blockIdx.x * 128;
    const int seg  = blockIdx.x >> 4;
    const int col0 = (blockIdx.x & 15) * 128;

    const int r0 = tid >> 3;
    const int c0 = tid & 7;
    const uint32_t stOff = (uint32_t)(((c0 ^ (r0 & 7)) << 4));

    const __nv_bfloat16* gA = A  + (size_t)(m0  + r0) * KS + c0 * 8;
    const __nv_bfloat16* gB = Bw + (size_t)(n0g + r0) * KS + c0 * 8;

    const int la = lane & 15, ha = lane >> 4;
    const int arow = wm * 32 + la;
    const uint32_t aswz = arow & 7;
    const int brow = wn * 64 + (lane & 7) + ((lane >> 4) & 1) * 8;
    const uint32_t bswz = brow & 7;
    const uint32_t bsel = (lane >> 3) & 1;

    uint32_t aoff[4], boff[4];
#pragma unroll
    for (int kh = 0; kh < 4; kh++) {
        aoff[kh] = arow * 128 + (((uint32_t)((2 * kh + ha) ^ aswz)) << 4);
        boff[kh] = 16384 + brow * 128 + (((uint32_t)((2 * kh + bsel) ^ bswz)) << 4);
    }

    float acc[2][8][4];
#pragma unroll
    for (int mi = 0; mi < 2; mi++)
#pragma unroll
        for (int ni = 0; ni < 8; ni++)
#pragma unroll
            for (int e = 0; e < 4; e++) acc[mi][ni][e] = 0.f;

#pragma unroll
    for (int s = 0; s < STAGES - 1; s++) {
        const uint32_t base = sb + s * STG_B;
        const int kc = s * BK;
#pragma unroll
        for (int r = 0; r < 4; r++) {
            const uint32_t so = (r0 + 32 * r) * 128 + stOff;
            cp16(base + so,         gA + (size_t)(32 * r) * KS + kc);
            cp16(base + 16384 + so, gB + (size_t)(32 * r) * KS + kc);
        }
        cp_commit();
    }

    int stage = 0;
    for (int it = 0; it < KITERS; it++) {
        if (it < KITERS - 1) cp_wait1(); else cp_wait0();
        __syncthreads();

        if (it + 2 < KITERS) {
            const int ps = (stage + 2 >= STAGES) ? stage + 2 - STAGES : stage + 2;
            const uint32_t base = sb + ps * STG_B;
            const int kc = (it + 2) * BK;
#pragma unroll
            for (int r = 0; r < 4; r++) {
                const uint32_t so = (r0 + 32 * r) * 128 + stOff;
                cp16(base + so,         gA + (size_t)(32 * r) * KS + kc);
                cp16(base + 16384 + so, gB + (size_t)(32 * r) * KS + kc);
            }
        }
        cp_commit();

        const uint32_t base = sb + stage * STG_B;
        stage = (stage + 1 >= STAGES) ? 0 : stage + 1;

#pragma unroll
        for (int kh = 0; kh < 4; kh++) {
            uint32_t av[2][4];
            ldsm4(av[0][0], av[0][1], av[0][2], av[0][3], base + aoff[kh]);
            ldsm4(av[1][0], av[1][1], av[1][2], av[1][3], base + aoff[kh] + 2048);

            uint32_t bv[4][4];
#pragma unroll
            for (int p = 0; p < 4; p++)
                ldsm4(bv[p][0], bv[p][1], bv[p][2], bv[p][3],
                      base + boff[kh] + p * 2048);

#pragma unroll
            for (int mi = 0; mi < 2; mi++)
#pragma unroll
                for (int ni = 0; ni < 8; ni++) {
                    const int p = ni >> 1;
                    const int h = (ni & 1) * 2;
                    mma16816(acc[mi][ni], av[mi], bv[p][h], bv[p][h + 1]);
                }
        }
    }

    const int g  = lane >> 2;
    const int tg = lane & 3;

    if (seg == 5) {
        if (wn == 0) {
#pragma unroll
            for (int mi = 0; mi < 2; mi++) {
                const int row = m0 + wm * 32 + mi * 16 + g;
#pragma unroll
                for (int ni = 0; ni < 2; ni++) {
                    const int col = ni * 8 + tg * 2;
                    const float b0 = bias_b[col], b1 = bias_b[col + 1];
                    Cb[(size_t)row * NH + col]           = fsig(acc[mi][ni][0] + b0);
                    Cb[(size_t)row * NH + col + 1]       = fsig(acc[mi][ni][1] + b1);
                    Cb[(size_t)(row + 8) * NH + col]     = fsig(acc[mi][ni][2] + b0);
                    Cb[(size_t)(row + 8) * NH + col + 1] = fsig(acc[mi][ni][3] + b1);
                }
            }
        }
        return;
    }

    float* C = (seg == 0) ? Cq : (seg == 1) ? Ck : (seg == 2) ? Cv
             : (seg == 3) ? Ca : Cg;
    const int et = (seg == 3) ? 1 : (seg == 4) ? 2 : 0;

#pragma unroll
    for (int mi = 0; mi < 2; mi++) {
        const int row = m0 + wm * 32 + mi * 16 + g;
#pragma unroll
        for (int ni = 0; ni < 8; ni++) {
            const int col = col0 + wn * 64 + ni * 8 + tg * 2;
            float v0 = acc[mi][ni][0], v1 = acc[mi][ni][1];
            float v2 = acc[mi][ni][2], v3 = acc[mi][ni][3];
            if (et == 1) {
                const float b0 = bias_a[col], b1 = bias_a[col + 1];
                v0 = fsig(v0 + b0); v1 = fsig(v1 + b1);
                v2 = fsig(v2 + b0); v3 = fsig(v3 + b1);
            } else if (et == 2) {
                v0 = fsig(v0); v1 = fsig(v1); v2 = fsig(v2); v3 = fsig(v3);
            }
            *(float2*)(C + (size_t)row * NC + col)       = make_float2(v0, v1);
            *(float2*)(C + (size_t)(row + 8) * NC + col) = make_float2(v2, v3);
        }
    }
}

// ------------------------------------------------------------------
// Split fp32 -> bf16 hi/lo, K-concatenated (float4 vectorized).
// ------------------------------------------------------------------
__device__ __forceinline__ void split_body(const float* __restrict__ in,
                                           __nv_bfloat16* __restrict__ out,
                                           int mode, int i)
{
    const int r  = i >> 9;
    const int k4 = (i << 2) & 2047;
    const float4 a = ((const float4*)in)[i];

    __nv_bfloat162 h01 = __floats2bfloat162_rn(a.x, a.y);
    __nv_bfloat162 h23 = __floats2bfloat162_rn(a.z, a.w);
    const float lx = a.x - __bfloat162float(__low2bfloat16(h01));
    const float ly = a.y - __bfloat162float(__high2bfloat16(h01));
    const float lz = a.z - __bfloat162float(__low2bfloat16(h23));
    const float lw = a.w - __bfloat162float(__high2bfloat16(h23));
    __nv_bfloat162 l01 = __floats2bfloat162_rn(lx, ly);
    __nv_bfloat162 l23 = __floats2bfloat162_rn(lz, lw);

    uint2 hp, lp;
    hp.x = *(const uint32_t*)&h01; hp.y = *(const uint32_t*)&h23;
    lp.x = *(const uint32_t*)&l01; lp.y = *(const uint32_t*)&l23;

    __nv_bfloat16* base = out + (size_t)r * KS + k4;
    *(uint2*)(base) = hp;
    if (mode == 0) { *(uint2*)(base + 2048) = lp; *(uint2*)(base + 4096) = hp; }
    else           { *(uint2*)(base + 2048) = hp; *(uint2*)(base + 4096) = lp; }
}

__global__ void __launch_bounds__(256)
split_all(const float* __restrict__ x,  const float* __restrict__ Wq,
          const float* __restrict__ Wk, const float* __restrict__ Wv,
          const float* __restrict__ Wa, const float* __restrict__ Wg,
          const float* __restrict__ Wo, const float* __restrict__ Wb,
          __nv_bfloat16* __restrict__ xs, __nv_bfloat16* __restrict__ ws)
{
    const int i = blockIdx.x * 256 + threadIdx.x;
    const int which = blockIdx.y;
    if (which == 7) {
        if (i >= (NH * ND) / 4) return;
        split_body(Wb, ws + 5 * WSTRIDE, 1, i);
        return;
    }
    if (i >= (NTOK * ND) / 4) return;
    if (which == 0)      split_body(x,  xs, 0, i);
    else if (which == 1) split_body(Wq, ws + 0 * WSTRIDE, 1, i);
    else if (which == 2) split_body(Wk, ws + 1 * WSTRIDE, 1, i);
    else if (which == 3) split_body(Wv, ws + 2 * WSTRIDE, 1, i);
    else if (which == 4) split_body(Wa, ws + 3 * WSTRIDE, 1, i);
    else if (which == 5) split_body(Wg, ws + 4 * WSTRIDE, 1, i);
    else                 split_body(Wo, ws + 5 * WSTRIDE + (size_t)128 * KS, 1, i);
}

// ------------------------------------------------------------------
// Fused causal depthwise conv (K=4) + bias + silu + scale.
// 4 consecutive tokens per thread.
// ------------------------------------------------------------------
__global__ void __launch_bounds__(256)
conv3(const float* __restrict__ q0, const float* __restrict__ k0,
      const float* __restrict__ v0,
      const float* __restrict__ wq, const float* __restrict__ wk,
      const float* __restrict__ wv,
      const float* __restrict__ bq, const float* __restrict__ bk,
      const float* __restrict__ bv,
      float* __restrict__ qc, float* __restrict__ kc, float* __restrict__ vc)
{
    const int i = blockIdx.x * 256 + threadIdx.x;
    if (i >= (NTOK / 4) * (NC / 4)) return;

    const float* in; const float* w; const float* bias; float* out; float scale;
    if (blockIdx.y == 0)      { in = q0; w = wq; bias = bq; out = qc; scale = 1.f; }
    else if (blockIdx.y == 1) { in = k0; w = wk; bias = bk; out = kc; scale = 0.08838834764831845f; }
    else                      { in = v0; w = wv; bias = bv; out = vc; scale = 1.f; }

    const int cg   = i & (NC / 4 - 1);
    const int quad = i >> 9;
    const int c    = cg * 4;
    const int t0   = (quad & (NT / 4 - 1)) * 4;
    const int b    = quad >> 8;

    const float4 w0 = ((const float4*)w)[c + 0];
    const float4 w1 = ((const float4*)w)[c + 1];
    const float4 w2 = ((const float4*)w)[c + 2];
    const float4 w3 = ((const float4*)w)[c + 3];
    const float4 bi = *(const float4*)(bias + c);

    const float* p = in + ((size_t)b * NT + t0) * NC + c;
    const float4 z = make_float4(0.f, 0.f, 0.f, 0.f);
    float4 r[7];
    r[0] = (t0 >= 3) ? *(const float4*)(p - 3 * NC) : z;
    r[1] = (t0 >= 2) ? *(const float4*)(p - 2 * NC) : z;
    r[2] = (t0 >= 1) ? *(const float4*)(p - NC)     : z;
    r[3] = *(const float4*)p;
    r[4] = *(const float4*)(p + NC);
    r[5] = *(const float4*)(p + 2 * NC);
    r[6] = *(const float4*)(p + 3 * NC);

    float* po = out + ((size_t)b * NT + t0) * NC + c;
#pragma unroll
    for (int o = 0; o < 4; o++) {
        float4 acc = bi;
        acc.x = fmaf(w0.x, r[o].x,     acc.x); acc.y = fmaf(w1.x, r[o].y,     acc.y);
        acc.z = fmaf(w2.x, r[o].z,     acc.z); acc.w = fmaf(w3.x, r[o].w,     acc.w);
        acc.x = fmaf(w0.y, r[o + 1].x, acc.x); acc.y = fmaf(w1.y, r[o + 1].y, acc.y);
        acc.z = fmaf(w2.y, r[o + 1].z, acc.z); acc.w = fmaf(w3.y, r[o + 1].w, acc.w);
        acc.x = fmaf(w0.z, r[o + 2].x, acc.x); acc.y = fmaf(w1.z, r[o + 2].y, acc.y);
        acc.z = fmaf(w2.z, r[o + 2].z, acc.z); acc.w = fmaf(w3.z, r[o + 2].w, acc.w);
        acc.x = fmaf(w0.w, r[o + 3].x, acc.x); acc.y = fmaf(w1.w, r[o + 3].y, acc.y);
        acc.z = fmaf(w2.w, r[o + 3].z, acc.z); acc.w = fmaf(w3.w, r[o + 3].w, acc.w);

        float4 rr;
        rr.x = acc.x * fsig(acc.x) * scale;
        rr.y = acc.y * fsig(acc.y) * scale;
        rr.z = acc.z * fsig(acc.z) * scale;
        rr.w = acc.w * fsig(acc.w) * scale;
        *(float4*)(po + (size_t)o * NC) = rr;
    }
}

// ------------------------------------------------------------------
// Recurrence: v-split 8, 2 chains per 256-thread CTA, packed f32x2,
// SCALAR side-recurrence for Sk:
//   R_{t+1} = a_t * W(t-1) + negcoef_t * kk_t
// where W(t) = S_{t+1}.k_{t+2} (fused-loop dot, reduced with a full
// step of slack) and kk_t = k_t.k_{t+1} (data-only, per-iteration).
// The recurrence-carried chain is 2 scalar FMAs per step.
// ------------------------------------------------------------------
__global__ void __launch_bounds__(256)
recur2(const float* __restrict__ qc, const float* __restrict__ kc,
       const float* __restrict__ vc, const float* __restrict__ ga,
       const float* __restrict__ gbeta, float* __restrict__ o1)
{
    const int bid   = blockIdx.x;        // 0..127
    const int b     = bid >> 6;
    const int h     = (bid >> 2) & 15;
    const int vpair = bid & 3;
    const int tid   = threadIdx.x;
    const int chain = tid >> 7;          // 0 or 1
    const int t128  = tid & 127;
    const int vloc  = t128 >> 3;         // 0..15
    const int kq    = t128 & 7;          // 0..7

    __shared__ __align__(16) float sk[8][160];
    __shared__ __align__(16) float sq[8][160];

    u64 S2[8];
#pragma unroll
    for (int j = 0; j < 8; j++) S2[j] = 0ull;

    const int kqchan = h * NDK + t128;
    const int vchan  = h * NDK + (vpair * 2 + chain) * 16 + vloc;
    const int sidx   = t128 + ((t128 >> 4) << 2);            // skew: +4 per 16
    const size_t tok0 = (size_t)b * NT;

    const float* stageSrc = (chain == 0) ? kc : qc;

#pragma unroll
    for (int tt = 0; tt < 4; tt++) {
        const float val = stageSrc[(tok0 + tt) * NC + kqchan];
        if (chain == 0) sk[tt][sidx] = val; else sq[tt][sidx] = val;
    }
    float v0c = vc[(tok0 + 0) * NC + vchan], a0c = ga[(tok0 + 0) * NC + vchan];
    float v1c = vc[(tok0 + 1) * NC + vchan], a1c = ga[(tok0 + 1) * NC + vchan];
    float v2c = vc[(tok0 + 2) * NC + vchan], a2c = ga[(tok0 + 2) * NC + vchan];
    float v3c = vc[(tok0 + 3) * NC + vchan], a3c = ga[(tok0 + 3) * NC + vchan];
    float be0 = gbeta[(tok0 + 0) * NH + h];
    float be1 = gbeta[(tok0 + 1) * NH + h];
    float be2 = gbeta[(tok0 + 2) * NH + h];
    float be3 = gbeta[(tok0 + 3) * NH + h];

    float R = 0.f;   // Sk for the CURRENT step (S_0 = 0)
    float W = 0.f;   // S_{t+1}.k_{t+2} from previous step (S-slack dot)

    // 16-element dot of two staged k buffers (per-thread partial + reduce)
    auto kkdot = [&](int bufA, int bufB) -> float {
        const ulonglong2* pa = (const ulonglong2*)&sk[bufA][kq * 20];
        const ulonglong2* pb = (const ulonglong2*)&sk[bufB][kq * 20];
        u64 acc0 = 0ull, acc1 = 0ull;
#pragma unroll
        for (int j = 0; j < 4; j++) {
            const ulonglong2 x = pa[j];
            const ulonglong2 y = pb[j];
            acc0 = fma2(x.x, y.x, acc0);
            acc1 = fma2(x.y, y.y, acc1);
        }
        float l, hi_;
        unpack2(add2(acc0, acc1), l, hi_);
        float s = l + hi_;
        s += __shfl_xor_sync(0xffffffffu, s, 1);
        s += __shfl_xor_sync(0xffffffffu, s, 2);
        s += __shfl_xor_sync(0xffffffffu, s, 4);
        return s;
    };

    // step t: buffers buf = t (k_t,q_t), buf2 = t+2 (k_{t+2} for W)
    auto step = [&](int buf, int buf2, float v_cur, float a_cur, float be_cur,
                    float kkv, int t) {
        const ulonglong2* kb = (const ulonglong2*)&sk[buf][kq * 20];
        const ulonglong2* qb = (const ulonglong2*)&sq[buf][kq * 20];
        const ulonglong2* k2 = (const ulonglong2*)&sk[buf2][kq * 20];

        const float negcoef = be_cur * (v_cur - R);
        // scalar side-recurrence: next step's Sk (2 FMAs; the only carried chain)
        R = fmaf(a_cur, W, negcoef * kkv);

        const u64 a2 = pack2(a_cur, a_cur);
        const u64 c2 = pack2(negcoef, negcoef);

        u64 oacc[2] = {0ull, 0ull};
        u64 wacc[2] = {0ull, 0ull};
#pragma unroll
        for (int j = 0; j < 4; j++) {
            const ulonglong2 kk = kb[j];
            const ulonglong2 qq = qb[j];
            const ulonglong2 nn = k2[j];
            S2[2*j]   = fma2(a2, S2[2*j],   mul2(c2, kk.x));
            oacc[0] = fma2(S2[2*j],   qq.x, oacc[0]);
            wacc[0] = fma2(S2[2*j],   nn.x, wacc[0]);
            S2[2*j+1] = fma2(a2, S2[2*j+1], mul2(c2, kk.y));
            oacc[1] = fma2(S2[2*j+1], qq.y, oacc[1]);
            wacc[1] = fma2(S2[2*j+1], nn.y, wacc[1]);
        }
        float ol, oh, wl, wh;
        unpack2(add2(oacc[0], oacc[1]), ol, oh);
        unpack2(add2(wacc[0], wacc[1]), wl, wh);

        float wn = wl + wh;                    // relaxed reduce (slack: 1 step)
        wn += __shfl_xor_sync(0xffffffffu, wn, 1);
        wn += __shfl_xor_sync(0xffffffffu, wn, 2);
        wn += __shfl_xor_sync(0xffffffffu, wn, 4);

        float op = ol + oh;
        op += __shfl_xor_sync(0xffffffffu, op, 1);
        op += __shfl_xor_sync(0xffffffffu, op, 2);
        op += __shfl_xor_sync(0xffffffffu, op, 4);
        if (kq == 0) o1[(tok0 + t) * NC + vchan] = op;

        W = wn;
    };

    for (int t = 0; t < NT; t += 2) {
        __syncthreads();   // bufs t..t+3 staged & visible; prior reads complete

        // data-only dots for the scalar side-recurrence (off critical path)
        const float kk0 = kkdot(t & 7, (t + 1) & 7);        // k_t . k_{t+1}
        const float kk1 = kkdot((t + 1) & 7, (t + 2) & 7);  // k_{t+1} . k_{t+2}

        // prefetch t+4, t+5 (regs)
        float s4 = 0.f, s5 = 0.f;
        float v4 = 0.f, a4 = 0.f, be4 = 0.f;
        float v5 = 0.f, a5 = 0.f, be5 = 0.f;
        const bool more = (t + 4 < NT);
        if (more) {
            const size_t i4 = (tok0 + t + 4) * NC;
            const size_t i5 = (tok0 + t + 5) * NC;
            s4 = stageSrc[i4 + kqchan];
            s5 = stageSrc[i5 + kqchan];
            v4 = vc[i4 + vchan]; a4 = ga[i4 + vchan];
            be4 = gbeta[(tok0 + t + 4) * NH + h];
            v5 = vc[i5 + vchan]; a5 = ga[i5 + vchan];
            be5 = gbeta[(tok0 + t + 5) * NH + h];
        }

        step(t & 7,       (t + 2) & 7, v0c, a0c, be0, kk0, t);
        step((t + 1) & 7, (t + 3) & 7, v1c, a1c, be1, kk1, t + 1);

        if (more) {
            if (chain == 0) {
                sk[(t + 4) & 7][sidx] = s4;
                sk[(t + 5) & 7][sidx] = s5;
            } else {
                sq[(t + 4) & 7][sidx] = s4;
                sq[(t + 5) & 7][sidx] = s5;
            }
        }
        v0c = v2c; a0c = a2c; be0 = be2;
        v1c = v3c; a1c = a3c; be1 = be3;
        v2c = v4;  a2c = a4;  be2 = be4;
        v3c = v5;  a3c = a5;  be3 = be5;
    }
}

// ------------------------------------------------------------------
// LayerNorm + gate + bf16 split directly into g_xs ([hi|lo|hi]).
// ------------------------------------------------------------------
__global__ void __launch_bounds__(128)
ln_gate_split(const float* __restrict__ o1, const float* __restrict__ gg,
              const float* __restrict__ ln_g, const float* __restrict__ ln_b,
              __nv_bfloat16* __restrict__ xs)
{
    const int bid = blockIdx.x;
    const int tok = bid >> 4, h = bid & 15;
    const int v = threadIdx.x, lane = v & 31, wid = v >> 5;
    const int chan = h * NDK + v;
    const size_t idx = (size_t)tok * NC + chan;

    const float o = o1[idx];

    __shared__ float red[8];
    float rs = o, rs2 = o * o;
#pragma unroll
    for (int off = 16; off > 0; off >>= 1) {
        rs  += __shfl_xor_sync(0xffffffffu, rs,  off);
        rs2 += __shfl_xor_sync(0xffffffffu, rs2, off);
    }
    if (lane == 0) { red[wid] = rs; red[4 + wid] = rs2; }
    __syncthreads();
    const float mu  = (red[0] + red[1] + red[2] + red[3]) * (1.f / 128.f);
    const float ms  = (red[4] + red[5] + red[6] + red[7]) * (1.f / 128.f);
    const float var = ms - mu * mu;
    const float y = ((o - mu) * rsqrtf(var + 1e-5f) * ln_g[v] + ln_b[v]) * gg[idx];

    const __nv_bfloat16 hbf = __float2bfloat16(y);
    const __nv_bfloat16 lbf = __float2bfloat16(y - __bfloat162float(hbf));
    __nv_bfloat16* base = xs + (size_t)tok * KS + chan;
    base[0]    = hbf;
    base[2048] = lbf;
    base[4096] = hbf;
}

// ------------------------------------------------------------------
// Launch
// ------------------------------------------------------------------
extern "C" void kernel_launch(void* const* d_in, const int* in_sizes, int n_in,
                              void* d_out, int out_size)
{
    const float* x        = (const float*)d_in[0];
    const float* Wq       = (const float*)d_in[1];
    const float* Wk       = (const float*)d_in[2];
    const float* Wv       = (const float*)d_in[3];
    const float* Wa       = (const float*)d_in[4];
    const float* ba       = (const float*)d_in[5];
    const float* Wb       = (const float*)d_in[6];
    const float* bb       = (const float*)d_in[7];
    const float* conv_q_w = (const float*)d_in[8];
    const float* conv_q_b = (const float*)d_in[9];
    const float* conv_k_w = (const float*)d_in[10];
    const float* conv_k_b = (const float*)d_in[11];
    const float* conv_v_w = (const float*)d_in[12];
    const float* conv_v_b = (const float*)d_in[13];
    const float* Wg       = (const float*)d_in[14];
    const float* ln_g     = (const float*)d_in[15];
    const float* ln_b     = (const float*)d_in[16];
    const float* Wo       = (const float*)d_in[17];
    float* out = (float*)d_out;

    __nv_bfloat16 *xs, *ws;
    float *q0, *k0, *v0, *qc, *kc, *vc, *pa, *pg, *po1, *pbeta;
    cudaGetSymbolAddress((void**)&xs,    g_xs);
    cudaGetSymbolAddress((void**)&ws,    g_ws);
    cudaGetSymbolAddress((void**)&q0,    g_q0);
    cudaGetSymbolAddress((void**)&k0,    g_k0);
    cudaGetSymbolAddress((void**)&v0,    g_v0);
    cudaGetSymbolAddress((void**)&qc,    g_qc);
    cudaGetSymbolAddress((void**)&kc,    g_kc);
    cudaGetSymbolAddress((void**)&vc,    g_vc);
    cudaGetSymbolAddress((void**)&pa,    g_a);
    cudaGetSymbolAddress((void**)&pg,    g_gt);
    cudaGetSymbolAddress((void**)&po1,   g_o1);
    cudaGetSymbolAddress((void**)&pbeta, g_bt);

    static bool attr_set = false;
    if (!attr_set) {
        cudaFuncSetAttribute(tgemm, cudaFuncAttributeMaxDynamicSharedMemorySize, TG_SMEM);
        attr_set = true;
    }

    __nv_bfloat16* wo_split = ws + 5 * WSTRIDE + (size_t)128 * KS;

    const int q4blk = ((NTOK * ND) / 4 + 255) / 256;       // 4096
    const int c4blk = ((NTOK / 4) * (NC / 4) + 255) / 256; // 1024

    // all splits (x + 6 big weights + Wb) in one launch
    split_all<<<dim3(q4blk, 8), 256>>>(x, Wq, Wk, Wv, Wa, Wg, Wo, Wb, xs, ws);

    // fused 6-output GEMM (q, k, v, a, g, beta) — grid.x = 81
    tgemm<<<dim3(81, 16), 256, TG_SMEM>>>(xs, ws, ba, bb,
                                          q0, k0, v0, pa, pg, pbeta);

    // fused conv + silu (q, k*DK^-0.5, v), 4 tokens per thread
    conv3<<<dim3(c4blk, 3), 256>>>(q0, k0, v0, conv_q_w, conv_k_w, conv_v_w,
                                   conv_q_b, conv_k_b, conv_v_b, qc, kc, vc);

    // recurrence: scalar side-recurrence Sk, 2 chains per CTA
    recur2<<<NB * NH * 4, 256>>>(qc, kc, vc, pa, pbeta, po1);
    ln_gate_split<<<NTOK * NH, 128>>>(po1, pg, ln_g, ln_b, xs);

    // output projection (seg = 0 -> plain store to out)
    tgemm<<<dim3(16, 16), 256, TG_SMEM>>>(xs, wo_split, nullptr, nullptr,
                                          out, out, out, out, out, out);
}

// round 16
// speedup vs baseline: 1.1564x; 1.1564x over previous
#include <cuda_runtime.h>
#include <cuda_bf16.h>
#include <math.h>
#include <stdint.h>

#define NB   2
#define NT   1024
#define ND   2048
#define NH   16
#define NDK  128
#define NTOK (NB*NT)      /* 2048 tokens */
#define NC   (NH*NDK)     /* 2048 channels */
#define KS   (3*ND)       /* 6144: split-precision K (hi|lo|hi) */
#define WSTRIDE ((size_t)NC*KS)

// ------------------------------------------------------------------
// Scratch (device globals; no runtime allocation allowed)
// ------------------------------------------------------------------
__device__ __nv_bfloat16 g_xs[(size_t)NTOK*KS];            // split activations
__device__ __nv_bfloat16 g_ws[6*WSTRIDE + (size_t)128*KS]; // split weights (+Wb pad)
__device__ float g_q0[NTOK*NC];
__device__ float g_k0[NTOK*NC];
__device__ float g_v0[NTOK*NC];
__device__ float g_qc[NTOK*NC];
__device__ float g_kc[NTOK*NC];
__device__ float g_vc[NTOK*NC];
__device__ float g_a [NTOK*NC];
__device__ float g_gt[NTOK*NC];
__device__ float g_o1[NTOK*NC];                   // reduced recurrence output
__device__ float g_bt[NTOK*NH];

// ==================================================================
// Helpers
// ==================================================================
__device__ __forceinline__ uint32_t smem_u32(const void* p) {
    uint32_t r;
    asm("{ .reg .u64 t; cvta.to.shared.u64 t, %1; cvt.u32.u64 %0, t; }"
        : "=r"(r) : "l"(p));
    return r;
}
__device__ __forceinline__ void cp16(uint32_t dst, const void* src) {
    asm volatile("cp.async.cg.shared.global [%0], [%1], 16;\n" :: "r"(dst), "l"(src));
}
__device__ __forceinline__ void cp_commit() {
    asm volatile("cp.async.commit_group;\n" ::: "memory");
}
__device__ __forceinline__ void cp_wait1() {
    asm volatile("cp.async.wait_group 1;\n" ::: "memory");
}
__device__ __forceinline__ void cp_wait0() {
    asm volatile("cp.async.wait_group 0;\n" ::: "memory");
}
__device__ __forceinline__ void ldsm4(uint32_t& r0, uint32_t& r1, uint32_t& r2,
                                      uint32_t& r3, uint32_t addr) {
    asm volatile("ldmatrix.sync.aligned.m8n8.x4.shared.b16 {%0,%1,%2,%3}, [%4];"
                 : "=r"(r0), "=r"(r1), "=r"(r2), "=r"(r3) : "r"(addr));
}
__device__ __forceinline__ void mma16816(float* d, const uint32_t* a,
                                         uint32_t b0, uint32_t b1) {
    asm volatile(
        "mma.sync.aligned.m16n8k16.row.col.f32.bf16.bf16.f32 "
        "{%0,%1,%2,%3}, {%4,%5,%6,%7}, {%8,%9}, {%0,%1,%2,%3};"
        : "+f"(d[0]), "+f"(d[1]), "+f"(d[2]), "+f"(d[3])
        : "r"(a[0]), "r"(a[1]), "r"(a[2]), "r"(a[3]), "r"(b0), "r"(b1));
}
__device__ __forceinline__ float fsig(float z) {
    return 1.f / (1.f + __expf(-z));
}

// ---- packed f32x2 (sm_100-family base feature) ----
typedef unsigned long long u64;
__device__ __forceinline__ u64 pack2(float lo, float hi) {
    u64 r; asm("mov.b64 %0, {%1, %2};" : "=l"(r) : "f"(lo), "f"(hi)); return r;
}
__device__ __forceinline__ void unpack2(u64 v, float& lo, float& hi) {
    asm("mov.b64 {%0, %1}, %2;" : "=f"(lo), "=f"(hi) : "l"(v));
}
__device__ __forceinline__ u64 fma2(u64 a, u64 b, u64 c) {
    u64 d; asm("fma.rn.f32x2 %0, %1, %2, %3;" : "=l"(d) : "l"(a), "l"(b), "l"(c));
    return d;
}
__device__ __forceinline__ u64 mul2(u64 a, u64 b) {
    u64 d; asm("mul.rn.f32x2 %0, %1, %2;" : "=l"(d) : "l"(a), "l"(b));
    return d;
}
__device__ __forceinline__ u64 add2(u64 a, u64 b) {
    u64 d; asm("add.rn.f32x2 %0, %1, %2;" : "=l"(d) : "l"(a), "l"(b));
    return d;
}

// ==================================================================
// Tensor-core GEMM (HMMA): fused 6-output projection (grid.x=81) or Wo (16)
// 128x128 tile, BK=64, 3-stage cp.async pipeline (96 KB smem), 8 warps.
// (Frozen R13 configuration.)
// ==================================================================
#define BK      64
#define KITERS  (KS/BK)      /* 96 */
#define STG_B   32768
#define STAGES  3
#define TG_SMEM (STAGES*STG_B)

__global__ void __launch_bounds__(256, 2)
tgemm(const __nv_bfloat16* __restrict__ A, const __nv_bfloat16* __restrict__ Bw,
      const float* __restrict__ bias_a, const float* __restrict__ bias_b,
      float* __restrict__ Cq, float* __restrict__ Ck, float* __restrict__ Cv,
      float* __restrict__ Ca, float* __restrict__ Cg, float* __restrict__ Cb)
{
    extern __shared__ __align__(1024) char smem[];
    const uint32_t sb = smem_u32(smem);

    const int tid  = threadIdx.x;
    const int lane = tid & 31;
    const int wid  = tid >> 5;
    const int wm   = wid & 3;
    const int wn   = wid >> 2;
    const int m0   = blockIdx.y * 128;
    const int n0g  = blockIdx.x * 128;
    const int seg  = blockIdx.x >> 4;
    const int col0 = (blockIdx.x & 15) * 128;

    const int r0 = tid >> 3;
    const int c0 = tid & 7;
    const uint32_t stOff = (uint32_t)(((c0 ^ (r0 & 7)) << 4));

    const __nv_bfloat16* gA = A  + (size_t)(m0  + r0) * KS + c0 * 8;
    const __nv_bfloat16* gB = Bw + (size_t)(n0g + r0) * KS + c0 * 8;

    const int la = lane & 15, ha = lane >> 4;
    const int arow = wm * 32 + la;
    const uint32_t aswz = arow & 7;
    const int brow = wn * 64 + (lane & 7) + ((lane >> 4) & 1) * 8;
    const uint32_t bswz = brow & 7;
    const uint32_t bsel = (lane >> 3) & 1;

    uint32_t aoff[4], boff[4];
#pragma unroll
    for (int kh = 0; kh < 4; kh++) {
        aoff[kh] = arow * 128 + (((uint32_t)((2 * kh + ha) ^ aswz)) << 4);
        boff[kh] = 16384 + brow * 128 + (((uint32_t)((2 * kh + bsel) ^ bswz)) << 4);
    }

    float acc[2][8][4];
#pragma unroll
    for (int mi = 0; mi < 2; mi++)
#pragma unroll
        for (int ni = 0; ni < 8; ni++)
#pragma unroll
            for (int e = 0; e < 4; e++) acc[mi][ni][e] = 0.f;

#pragma unroll
    for (int s = 0; s < STAGES - 1; s++) {
        const uint32_t base = sb + s * STG_B;
        const int kc = s * BK;
#pragma unroll
        for (int r = 0; r < 4; r++) {
            const uint32_t so = (r0 + 32 * r) * 128 + stOff;
            cp16(base + so,         gA + (size_t)(32 * r) * KS + kc);
            cp16(base + 16384 + so, gB + (size_t)(32 * r) * KS + kc);
        }
        cp_commit();
    }

    int stage = 0;
    for (int it = 0; it < KITERS; it++) {
        if (it < KITERS - 1) cp_wait1(); else cp_wait0();
        __syncthreads();

        if (it + 2 < KITERS) {
            const int ps = (stage + 2 >= STAGES) ? stage + 2 - STAGES : stage + 2;
            const uint32_t base = sb + ps * STG_B;
            const int kc = (it + 2) * BK;
#pragma unroll
            for (int r = 0; r < 4; r++) {
                const uint32_t so = (r0 + 32 * r) * 128 + stOff;
                cp16(base + so,         gA + (size_t)(32 * r) * KS + kc);
                cp16(base + 16384 + so, gB + (size_t)(32 * r) * KS + kc);
            }
        }
        cp_commit();

        const uint32_t base = sb + stage * STG_B;
        stage = (stage + 1 >= STAGES) ? 0 : stage + 1;

#pragma unroll
        for (int kh = 0; kh < 4; kh++) {
            uint32_t av[2][4];
            ldsm4(av[0][0], av[0][1], av[0][2], av[0][3], base + aoff[kh]);
            ldsm4(av[1][0], av[1][1], av[1][2], av[1][3], base + aoff[kh] + 2048);

            uint32_t bv[4][4];
#pragma unroll
            for (int p = 0; p < 4; p++)
                ldsm4(bv[p][0], bv[p][1], bv[p][2], bv[p][3],
                      base + boff[kh] + p * 2048);

#pragma unroll
            for (int mi = 0; mi < 2; mi++)
#pragma unroll
                for (int ni = 0; ni < 8; ni++) {
                    const int p = ni >> 1;
                    const int h = (ni & 1) * 2;
                    mma16816(acc[mi][ni], av[mi], bv[p][h], bv[p][h + 1]);
                }
        }
    }

    const int g  = lane >> 2;
    const int tg = lane & 3;

    if (seg == 5) {
        if (wn == 0) {
#pragma unroll
            for (int mi = 0; mi < 2; mi++) {
                const int row = m0 + wm * 32 + mi * 16 + g;
#pragma unroll
                for (int ni = 0; ni < 2; ni++) {
                    const int col = ni * 8 + tg * 2;
                    const float b0 = bias_b[col], b1 = bias_b[col + 1];
                    Cb[(size_t)row * NH + col]           = fsig(acc[mi][ni][0] + b0);
                    Cb[(size_t)row * NH + col + 1]       = fsig(acc[mi][ni][1] + b1);
                    Cb[(size_t)(row + 8) * NH + col]     = fsig(acc[mi][ni][2] + b0);
                    Cb[(size_t)(row + 8) * NH + col + 1] = fsig(acc[mi][ni][3] + b1);
                }
            }
        }
        return;
    }

    float* C = (seg == 0) ? Cq : (seg == 1) ? Ck : (seg == 2) ? Cv
             : (seg == 3) ? Ca : Cg;
    const int et = (seg == 3) ? 1 : (seg == 4) ? 2 : 0;

#pragma unroll
    for (int mi = 0; mi < 2; mi++) {
        const int row = m0 + wm * 32 + mi * 16 + g;
#pragma unroll
        for (int ni = 0; ni < 8; ni++) {
            const int col = col0 + wn * 64 + ni * 8 + tg * 2;
            float v0 = acc[mi][ni][0], v1 = acc[mi][ni][1];
            float v2 = acc[mi][ni][2], v3 = acc[mi][ni][3];
            if (et == 1) {
                const float b0 = bias_a[col], b1 = bias_a[col + 1];
                v0 = fsig(v0 + b0); v1 = fsig(v1 + b1);
                v2 = fsig(v2 + b0); v3 = fsig(v3 + b1);
            } else if (et == 2) {
                v0 = fsig(v0); v1 = fsig(v1); v2 = fsig(v2); v3 = fsig(v3);
            }
            *(float2*)(C + (size_t)row * NC + col)       = make_float2(v0, v1);
            *(float2*)(C + (size_t)(row + 8) * NC + col) = make_float2(v2, v3);
        }
    }
}

// ------------------------------------------------------------------
// Split fp32 -> bf16 hi/lo, K-concatenated (float4 vectorized).
// ------------------------------------------------------------------
__device__ __forceinline__ void split_body(const float* __restrict__ in,
                                           __nv_bfloat16* __restrict__ out,
                                           int mode, int i)
{
    const int r  = i >> 9;
    const int k4 = (i << 2) & 2047;
    const float4 a = ((const float4*)in)[i];

    __nv_bfloat162 h01 = __floats2bfloat162_rn(a.x, a.y);
    __nv_bfloat162 h23 = __floats2bfloat162_rn(a.z, a.w);
    const float lx = a.x - __bfloat162float(__low2bfloat16(h01));
    const float ly = a.y - __bfloat162float(__high2bfloat16(h01));
    const float lz = a.z - __bfloat162float(__low2bfloat16(h23));
    const float lw = a.w - __bfloat162float(__high2bfloat16(h23));
    __nv_bfloat162 l01 = __floats2bfloat162_rn(lx, ly);
    __nv_bfloat162 l23 = __floats2bfloat162_rn(lz, lw);

    uint2 hp, lp;
    hp.x = *(const uint32_t*)&h01; hp.y = *(const uint32_t*)&h23;
    lp.x = *(const uint32_t*)&l01; lp.y = *(const uint32_t*)&l23;

    __nv_bfloat16* base = out + (size_t)r * KS + k4;
    *(uint2*)(base) = hp;
    if (mode == 0) { *(uint2*)(base + 2048) = lp; *(uint2*)(base + 4096) = hp; }
    else           { *(uint2*)(base + 2048) = hp; *(uint2*)(base + 4096) = lp; }
}

__global__ void __launch_bounds__(256)
split_all(const float* __restrict__ x,  const float* __restrict__ Wq,
          const float* __restrict__ Wk, const float* __restrict__ Wv,
          const float* __restrict__ Wa, const float* __restrict__ Wg,
          const float* __restrict__ Wo, const float* __restrict__ Wb,
          __nv_bfloat16* __restrict__ xs, __nv_bfloat16* __restrict__ ws)
{
    const int i = blockIdx.x * 256 + threadIdx.x;
    const int which = blockIdx.y;
    if (which == 7) {
        if (i >= (NH * ND) / 4) return;
        split_body(Wb, ws + 5 * WSTRIDE, 1, i);
        return;
    }
    if (i >= (NTOK * ND) / 4) return;
    if (which == 0)      split_body(x,  xs, 0, i);
    else if (which == 1) split_body(Wq, ws + 0 * WSTRIDE, 1, i);
    else if (which == 2) split_body(Wk, ws + 1 * WSTRIDE, 1, i);
    else if (which == 3) split_body(Wv, ws + 2 * WSTRIDE, 1, i);
    else if (which == 4) split_body(Wa, ws + 3 * WSTRIDE, 1, i);
    else if (which == 5) split_body(Wg, ws + 4 * WSTRIDE, 1, i);
    else                 split_body(Wo, ws + 5 * WSTRIDE + (size_t)128 * KS, 1, i);
}

// ------------------------------------------------------------------
// Fused causal depthwise conv (K=4) + bias + silu + scale.
// 4 consecutive tokens per thread.
// ------------------------------------------------------------------
__global__ void __launch_bounds__(256)
conv3(const float* __restrict__ q0, const float* __restrict__ k0,
      const float* __restrict__ v0,
      const float* __restrict__ wq, const float* __restrict__ wk,
      const float* __restrict__ wv,
      const float* __restrict__ bq, const float* __restrict__ bk,
      const float* __restrict__ bv,
      float* __restrict__ qc, float* __restrict__ kc, float* __restrict__ vc)
{
    const int i = blockIdx.x * 256 + threadIdx.x;
    if (i >= (NTOK / 4) * (NC / 4)) return;

    const float* in; const float* w; const float* bias; float* out; float scale;
    if (blockIdx.y == 0)      { in = q0; w = wq; bias = bq; out = qc; scale = 1.f; }
    else if (blockIdx.y == 1) { in = k0; w = wk; bias = bk; out = kc; scale = 0.08838834764831845f; }
    else                      { in = v0; w = wv; bias = bv; out = vc; scale = 1.f; }

    const int cg   = i & (NC / 4 - 1);
    const int quad = i >> 9;
    const int c    = cg * 4;
    const int t0   = (quad & (NT / 4 - 1)) * 4;
    const int b    = quad >> 8;

    const float4 w0 = ((const float4*)w)[c + 0];
    const float4 w1 = ((const float4*)w)[c + 1];
    const float4 w2 = ((const float4*)w)[c + 2];
    const float4 w3 = ((const float4*)w)[c + 3];
    const float4 bi = *(const float4*)(bias + c);

    const float* p = in + ((size_t)b * NT + t0) * NC + c;
    const float4 z = make_float4(0.f, 0.f, 0.f, 0.f);
    float4 r[7];
    r[0] = (t0 >= 3) ? *(const float4*)(p - 3 * NC) : z;
    r[1] = (t0 >= 2) ? *(const float4*)(p - 2 * NC) : z;
    r[2] = (t0 >= 1) ? *(const float4*)(p - NC)     : z;
    r[3] = *(const float4*)p;
    r[4] = *(const float4*)(p + NC);
    r[5] = *(const float4*)(p + 2 * NC);
    r[6] = *(const float4*)(p + 3 * NC);

    float* po = out + ((size_t)b * NT + t0) * NC + c;
#pragma unroll
    for (int o = 0; o < 4; o++) {
        float4 acc = bi;
        acc.x = fmaf(w0.x, r[o].x,     acc.x); acc.y = fmaf(w1.x, r[o].y,     acc.y);
        acc.z = fmaf(w2.x, r[o].z,     acc.z); acc.w = fmaf(w3.x, r[o].w,     acc.w);
        acc.x = fmaf(w0.y, r[o + 1].x, acc.x); acc.y = fmaf(w1.y, r[o + 1].y, acc.y);
        acc.z = fmaf(w2.y, r[o + 1].z, acc.z); acc.w = fmaf(w3.y, r[o + 1].w, acc.w);
        acc.x = fmaf(w0.z, r[o + 2].x, acc.x); acc.y = fmaf(w1.z, r[o + 2].y, acc.y);
        acc.z = fmaf(w2.z, r[o + 2].z, acc.z); acc.w = fmaf(w3.z, r[o + 2].w, acc.w);
        acc.x = fmaf(w0.w, r[o + 3].x, acc.x); acc.y = fmaf(w1.w, r[o + 3].y, acc.y);
        acc.z = fmaf(w2.w, r[o + 3].z, acc.z); acc.w = fmaf(w3.w, r[o + 3].w, acc.w);

        float4 rr;
        rr.x = acc.x * fsig(acc.x) * scale;
        rr.y = acc.y * fsig(acc.y) * scale;
        rr.z = acc.z * fsig(acc.z) * scale;
        rr.w = acc.w * fsig(acc.w) * scale;
        *(float4*)(po + (size_t)o * NC) = rr;
    }
}

// ------------------------------------------------------------------
// Recurrence: v-split 8, TWO chains per 256-thread CTA (R14 config),
// packed f32x2, pipelined Sk. S-update written as
//   S = fma2(c2, k, mul2(a2, S))   [a*S independent of the reduce]
// so the reduce-carried chain is negcoef -> c2 -> one fma2.
// ------------------------------------------------------------------
__global__ void __launch_bounds__(256)
recur2(const float* __restrict__ qc, const float* __restrict__ kc,
       const float* __restrict__ vc, const float* __restrict__ ga,
       const float* __restrict__ gbeta, float* __restrict__ o1)
{
    const int bid   = blockIdx.x;        // 0..127
    const int b     = bid >> 6;
    const int h     = (bid >> 2) & 15;
    const int vpair = bid & 3;
    const int tid   = threadIdx.x;
    const int chain = tid >> 7;          // 0 or 1
    const int t128  = tid & 127;
    const int vloc  = t128 >> 3;         // 0..15
    const int kq    = t128 & 7;          // 0..7

    __shared__ __align__(16) float sk[8][160];
    __shared__ __align__(16) float sq[8][160];

    u64 S2[8];
#pragma unroll
    for (int j = 0; j < 8; j++) S2[j] = 0ull;

    const int kqchan = h * NDK + t128;
    const int vchan  = h * NDK + (vpair * 2 + chain) * 16 + vloc;
    const int sidx   = t128 + ((t128 >> 4) << 2);            // skew: +4 per 16
    const size_t tok0 = (size_t)b * NT;

    const float* stageSrc = (chain == 0) ? kc : qc;

#pragma unroll
    for (int tt = 0; tt < 4; tt++) {
        const float val = stageSrc[(tok0 + tt) * NC + kqchan];
        if (chain == 0) sk[tt][sidx] = val; else sq[tt][sidx] = val;
    }
    float v0c = vc[(tok0 + 0) * NC + vchan], a0c = ga[(tok0 + 0) * NC + vchan];
    float v1c = vc[(tok0 + 1) * NC + vchan], a1c = ga[(tok0 + 1) * NC + vchan];
    float v2c = vc[(tok0 + 2) * NC + vchan], a2c = ga[(tok0 + 2) * NC + vchan];
    float v3c = vc[(tok0 + 3) * NC + vchan], a3c = ga[(tok0 + 3) * NC + vchan];
    float be0 = gbeta[(tok0 + 0) * NH + h];
    float be1 = gbeta[(tok0 + 1) * NH + h];
    float be2 = gbeta[(tok0 + 2) * NH + h];
    float be3 = gbeta[(tok0 + 3) * NH + h];

    float Skr = 0.f;

    auto step = [&](int buf, int nbuf, float v_cur, float a_cur, float be_cur, int t) {
        const ulonglong2* kb = (const ulonglong2*)&sk[buf][kq * 20];
        const ulonglong2* qb = (const ulonglong2*)&sq[buf][kq * 20];
        const ulonglong2* kn = (const ulonglong2*)&sk[nbuf][kq * 20];

        const float negcoef = be_cur * (v_cur - Skr);
        const u64 a2 = pack2(a_cur, a_cur);
        const u64 c2 = pack2(negcoef, negcoef);

        u64 oacc[4] = {0ull, 0ull, 0ull, 0ull};
        u64 sacc[4] = {0ull, 0ull, 0ull, 0ull};
#pragma unroll
        for (int j = 0; j < 4; j++) {
            const ulonglong2 kk = kb[j];
            const ulonglong2 qq = qb[j];
            const ulonglong2 nn = kn[j];
            S2[2*j]   = fma2(c2, kk.x, mul2(a2, S2[2*j]));
            oacc[(2*j)   & 3] = fma2(S2[2*j],   qq.x, oacc[(2*j)   & 3]);
            sacc[(2*j)   & 3] = fma2(S2[2*j],   nn.x, sacc[(2*j)   & 3]);
            S2[2*j+1] = fma2(c2, kk.y, mul2(a2, S2[2*j+1]));
            oacc[(2*j+1) & 3] = fma2(S2[2*j+1], qq.y, oacc[(2*j+1) & 3]);
            sacc[(2*j+1) & 3] = fma2(S2[2*j+1], nn.y, sacc[(2*j+1) & 3]);
        }
        const u64 osum = add2(add2(oacc[0], oacc[1]), add2(oacc[2], oacc[3]));
        const u64 ssum = add2(add2(sacc[0], sacc[1]), add2(sacc[2], sacc[3]));
        float ol, oh, sl, sh;
        unpack2(osum, ol, oh);
        unpack2(ssum, sl, sh);
        float skn = sl + sh;
        skn += __shfl_xor_sync(0xffffffffu, skn, 1);
        skn += __shfl_xor_sync(0xffffffffu, skn, 2);
        skn += __shfl_xor_sync(0xffffffffu, skn, 4);

        float op = ol + oh;
        op += __shfl_xor_sync(0xffffffffu, op, 1);
        op += __shfl_xor_sync(0xffffffffu, op, 2);
        op += __shfl_xor_sync(0xffffffffu, op, 4);
        if (kq == 0) o1[(tok0 + t) * NC + vchan] = op;

        Skr = skn;
    };

    for (int t = 0; t < NT; t += 2) {
        __syncthreads();   // bufs t..t+3 staged & visible; prior reads complete

        // prefetch t+4, t+5 (regs)
        float s4 = 0.f, s5 = 0.f;
        float v4 = 0.f, a4 = 0.f, be4 = 0.f;
        float v5 = 0.f, a5 = 0.f, be5 = 0.f;
        const bool more = (t + 4 < NT);
        if (more) {
            const size_t i4 = (tok0 + t + 4) * NC;
            const size_t i5 = (tok0 + t + 5) * NC;
            s4 = stageSrc[i4 + kqchan];
            s5 = stageSrc[i5 + kqchan];
            v4 = vc[i4 + vchan]; a4 = ga[i4 + vchan];
            be4 = gbeta[(tok0 + t + 4) * NH + h];
            v5 = vc[i5 + vchan]; a5 = ga[i5 + vchan];
            be5 = gbeta[(tok0 + t + 5) * NH + h];
        }

        step(t & 7,       (t + 1) & 7, v0c, a0c, be0, t);
        step((t + 1) & 7, (t + 2) & 7, v1c, a1c, be1, t + 1);

        if (more) {
            if (chain == 0) {
                sk[(t + 4) & 7][sidx] = s4;
                sk[(t + 5) & 7][sidx] = s5;
            } else {
                sq[(t + 4) & 7][sidx] = s4;
                sq[(t + 5) & 7][sidx] = s5;
            }
        }
        v0c = v2c; a0c = a2c; be0 = be2;
        v1c = v3c; a1c = a3c; be1 = be3;
        v2c = v4;  a2c = a4;  be2 = be4;
        v3c = v5;  a3c = a5;  be3 = be5;
    }
}

// ------------------------------------------------------------------
// LayerNorm + gate + bf16 split directly into g_xs ([hi|lo|hi]).
// ------------------------------------------------------------------
__global__ void __launch_bounds__(128)
ln_gate_split(const float* __restrict__ o1, const float* __restrict__ gg,
              const float* __restrict__ ln_g, const float* __restrict__ ln_b,
              __nv_bfloat16* __restrict__ xs)
{
    const int bid = blockIdx.x;
    const int tok = bid >> 4, h = bid & 15;
    const int v = threadIdx.x, lane = v & 31, wid = v >> 5;
    const int chan = h * NDK + v;
    const size_t idx = (size_t)tok * NC + chan;

    const float o = o1[idx];

    __shared__ float red[8];
    float rs = o, rs2 = o * o;
#pragma unroll
    for (int off = 16; off > 0; off >>= 1) {
        rs  += __shfl_xor_sync(0xffffffffu, rs,  off);
        rs2 += __shfl_xor_sync(0xffffffffu, rs2, off);
    }
    if (lane == 0) { red[wid] = rs; red[4 + wid] = rs2; }
    __syncthreads();
    const float mu  = (red[0] + red[1] + red[2] + red[3]) * (1.f / 128.f);
    const float ms  = (red[4] + red[5] + red[6] + red[7]) * (1.f / 128.f);
    const float var = ms - mu * mu;
    const float y = ((o - mu) * rsqrtf(var + 1e-5f) * ln_g[v] + ln_b[v]) * gg[idx];

    const __nv_bfloat16 hbf = __float2bfloat16(y);
    const __nv_bfloat16 lbf = __float2bfloat16(y - __bfloat162float(hbf));
    __nv_bfloat16* base = xs + (size_t)tok * KS + chan;
    base[0]    = hbf;
    base[2048] = lbf;
    base[4096] = hbf;
}

// ------------------------------------------------------------------
// Launch
// ------------------------------------------------------------------
extern "C" void kernel_launch(void* const* d_in, const int* in_sizes, int n_in,
                              void* d_out, int out_size)
{
    const float* x        = (const float*)d_in[0];
    const float* Wq       = (const float*)d_in[1];
    const float* Wk       = (const float*)d_in[2];
    const float* Wv       = (const float*)d_in[3];
    const float* Wa       = (const float*)d_in[4];
    const float* ba       = (const float*)d_in[5];
    const float* Wb       = (const float*)d_in[6];
    const float* bb       = (const float*)d_in[7];
    const float* conv_q_w = (const float*)d_in[8];
    const float* conv_q_b = (const float*)d_in[9];
    const float* conv_k_w = (const float*)d_in[10];
    const float* conv_k_b = (const float*)d_in[11];
    const float* conv_v_w = (const float*)d_in[12];
    const float* conv_v_b = (const float*)d_in[13];
    const float* Wg       = (const float*)d_in[14];
    const float* ln_g     = (const float*)d_in[15];
    const float* ln_b     = (const float*)d_in[16];
    const float* Wo       = (const float*)d_in[17];
    float* out = (float*)d_out;

    __nv_bfloat16 *xs, *ws;
    float *q0, *k0, *v0, *qc, *kc, *vc, *pa, *pg, *po1, *pbeta;
    cudaGetSymbolAddress((void**)&xs,    g_xs);
    cudaGetSymbolAddress((void**)&ws,    g_ws);
    cudaGetSymbolAddress((void**)&q0,    g_q0);
    cudaGetSymbolAddress((void**)&k0,    g_k0);
    cudaGetSymbolAddress((void**)&v0,    g_v0);
    cudaGetSymbolAddress((void**)&qc,    g_qc);
    cudaGetSymbolAddress((void**)&kc,    g_kc);
    cudaGetSymbolAddress((void**)&vc,    g_vc);
    cudaGetSymbolAddress((void**)&pa,    g_a);
    cudaGetSymbolAddress((void**)&pg,    g_gt);
    cudaGetSymbolAddress((void**)&po1,   g_o1);
    cudaGetSymbolAddress((void**)&pbeta, g_bt);

    static bool attr_set = false;
    if (!attr_set) {
        cudaFuncSetAttribute(tgemm, cudaFuncAttributeMaxDynamicSharedMemorySize, TG_SMEM);
        attr_set = true;
    }

    __nv_bfloat16* wo_split = ws + 5 * WSTRIDE + (size_t)128 * KS;

    const int q4blk = ((NTOK * ND) / 4 + 255) / 256;       // 4096
    const int c4blk = ((NTOK / 4) * (NC / 4) + 255) / 256; // 1024

    // all splits (x + 6 big weights + Wb) in one launch
    split_all<<<dim3(q4blk, 8), 256>>>(x, Wq, Wk, Wv, Wa, Wg, Wo, Wb, xs, ws);

    // fused 6-output GEMM (q, k, v, a, g, beta) — grid.x = 81
    tgemm<<<dim3(81, 16), 256, TG_SMEM>>>(xs, ws, ba, bb,
                                          q0, k0, v0, pa, pg, pbeta);

    // fused conv + silu (q, k*DK^-0.5, v), 4 tokens per thread
    conv3<<<dim3(c4blk, 3), 256>>>(q0, k0, v0, conv_q_w, conv_k_w, conv_v_w,
                                   conv_q_b, conv_k_b, conv_v_b, qc, kc, vc);

    // recurrence: v-split 8, 2 chains per CTA (R14 config + off-chain a*S)
    recur2<<<NB * NH * 4, 256>>>(qc, kc, vc, pa, pbeta, po1);
    ln_gate_split<<<NTOK * NH, 128>>>(po1, pg, ln_g, ln_b, xs);

    // output projection (seg = 0 -> plain store to out)
    tgemm<<<dim3(16, 16), 256, TG_SMEM>>>(xs, wo_split, nullptr, nullptr,
                                          out, out, out, out, out, out);
}